// round 1
// baseline (speedup 1.0000x reference)
#include <cuda_runtime.h>
#include <cstdint>

// Problem constants
#define BB 128   // batch
#define SS 128   // support size
#define NN 784   // 28*28 feats
#define DD 512   // feature dim

#define GAMMA 10.0f
#define N_ITERS 10
// matches np.float32(7/3 - 4/3 - 1) evaluated in float64 then cast
#define EPS_F 2.2204460492503131e-16f
#define QF (1.0f / 784.0f)
#define PF (1.0f / 128.0f)

// ---------------- device scratch (no dynamic allocation allowed) ----------------
__device__ float g_K[(size_t)BB * SS * NN];   // 51.4 MB, exp kernel matrix
__device__ float g_tn[SS * DD];               // normalized target support
__device__ float g_rn[BB * NN];               // inverse norms of features

// ---------------- kernel 1: normalize target support ----------------
__global__ void norm_target_kernel(const float* __restrict__ t) {
    int s = blockIdx.x;           // 128 blocks
    int tid = threadIdx.x;        // 128 threads, one float4 each
    __shared__ float red[4];
    const float4* tr = (const float4*)(t + (size_t)s * DD);
    float4 v = tr[tid];
    float ss = v.x * v.x + v.y * v.y + v.z * v.z + v.w * v.w;
    #pragma unroll
    for (int o = 16; o; o >>= 1) ss += __shfl_xor_sync(0xffffffffu, ss, o);
    if ((tid & 31) == 0) red[tid >> 5] = ss;
    __syncthreads();
    float inv = rsqrtf(red[0] + red[1] + red[2] + red[3]);
    float4* out = (float4*)(g_tn + (size_t)s * DD);
    v.x *= inv; v.y *= inv; v.z *= inv; v.w *= inv;
    out[tid] = v;
}

// ---------------- kernel 2: feature inverse norms ----------------
// one warp per (b,n) row of 512 floats
__global__ void feat_norm_kernel(const float* __restrict__ f) {
    int row = blockIdx.x * 8 + (threadIdx.x >> 5);   // grid covers B*N rows exactly
    int lane = threadIdx.x & 31;
    const float4* fr = (const float4*)(f + (size_t)row * DD);
    float ss = 0.f;
    #pragma unroll
    for (int i = lane; i < DD / 4; i += 32) {
        float4 v = fr[i];
        ss += v.x * v.x + v.y * v.y + v.z * v.z + v.w * v.w;
    }
    #pragma unroll
    for (int o = 16; o; o >>= 1) ss += __shfl_xor_sync(0xffffffffu, ss, o);
    if (lane == 0) g_rn[row] = rsqrtf(ss);
}

// ---------------- kernel 3: batched GEMM + exp epilogue ----------------
// K[b,s,n] = exp(-GAMMA * (2 - 2 * dot(tn[s], f[b,n]) * rn[b,n]))
//          = exp(20 * dot * rn - 20)
// Tile: 128 (S, full) x 128 (N) per CTA, 256 threads, 8x8 per thread, TK=32.
#define TK 32
#define APAD 4
__global__ __launch_bounds__(256) void gemm_exp_kernel(const float* __restrict__ f) {
    const int b  = blockIdx.y;
    const int n0 = blockIdx.x * 128;          // 7 tiles: 0..896, valid n < 784
    const int tid = threadIdx.x;
    const int tx = tid & 15;                  // n direction, 8 each
    const int ty = tid >> 4;                  // s direction, 8 each

    __shared__ float As[TK][128 + APAD];
    __shared__ float Bs[TK][128 + APAD];

    float acc[8][8];
    #pragma unroll
    for (int j = 0; j < 8; j++)
        #pragma unroll
        for (int i = 0; i < 8; i++) acc[j][i] = 0.f;

    const float* fb = f + (size_t)b * NN * DD;

    for (int k0 = 0; k0 < DD; k0 += TK) {
        // load A tile: 128 s x 32 k (g_tn), 1024 float4 slots, 4 per thread
        #pragma unroll
        for (int p = 0; p < 4; p++) {
            int slot = tid + p * 256;
            int s  = slot >> 3;
            int kk = (slot & 7) * 4;
            float4 va = *(const float4*)&g_tn[(size_t)s * DD + k0 + kk];
            As[kk + 0][s] = va.x; As[kk + 1][s] = va.y;
            As[kk + 2][s] = va.z; As[kk + 3][s] = va.w;
        }
        // load B tile: 128 n x 32 k (features), guarded on n < 784
        #pragma unroll
        for (int p = 0; p < 4; p++) {
            int slot = tid + p * 256;
            int nl = slot >> 3;
            int kk = (slot & 7) * 4;
            int n  = n0 + nl;
            float4 vb = make_float4(0.f, 0.f, 0.f, 0.f);
            if (n < NN) vb = *(const float4*)&fb[(size_t)n * DD + k0 + kk];
            Bs[kk + 0][nl] = vb.x; Bs[kk + 1][nl] = vb.y;
            Bs[kk + 2][nl] = vb.z; Bs[kk + 3][nl] = vb.w;
        }
        __syncthreads();

        #pragma unroll
        for (int k = 0; k < TK; k++) {
            float a[8], bb[8];
            float4 a0 = *(const float4*)&As[k][ty * 8];
            float4 a1 = *(const float4*)&As[k][ty * 8 + 4];
            float4 b0 = *(const float4*)&Bs[k][tx * 8];
            float4 b1 = *(const float4*)&Bs[k][tx * 8 + 4];
            a[0]=a0.x; a[1]=a0.y; a[2]=a0.z; a[3]=a0.w;
            a[4]=a1.x; a[5]=a1.y; a[6]=a1.z; a[7]=a1.w;
            bb[0]=b0.x; bb[1]=b0.y; bb[2]=b0.z; bb[3]=b0.w;
            bb[4]=b1.x; bb[5]=b1.y; bb[6]=b1.z; bb[7]=b1.w;
            #pragma unroll
            for (int j = 0; j < 8; j++)
                #pragma unroll
                for (int i = 0; i < 8; i++)
                    acc[j][i] = fmaf(a[j], bb[i], acc[j][i]);
        }
        __syncthreads();
    }

    // epilogue: scale by rn, exp, store K
    #pragma unroll
    for (int i = 0; i < 8; i++) {
        int n = n0 + tx * 8 + i;
        if (n >= NN) continue;
        float rn = g_rn[(size_t)b * NN + n];
        float sc = 20.f * rn;
        #pragma unroll
        for (int j = 0; j < 8; j++) {
            int s = ty * 8 + j;
            g_K[((size_t)b * SS + s) * NN + n] = __expf(fmaf(acc[j][i], sc, -20.f));
        }
    }
}

// ---------------- kernel 4: Sinkhorn iterations + Pi (one CTA per batch) ----------------
__global__ __launch_bounds__(512) void sinkhorn_kernel(float* __restrict__ Pi) {
    const int b = blockIdx.x;
    const int tid = threadIdx.x;
    const float* __restrict__ Kb = g_K + (size_t)b * SS * NN;

    __shared__ float su[SS];
    __shared__ float sv[NN];

    if (tid < SS) su[tid] = 1.0f;
    __syncthreads();

    const int warp = tid >> 5;
    const int lane = tid & 31;

    for (int it = 0; it < N_ITERS; it++) {
        // v[n] = q / (sum_s u[s] * K[s,n] + eps)
        for (int n = tid; n < NN; n += 512) {
            float acc = 0.f;
            #pragma unroll 8
            for (int s = 0; s < SS; s++)
                acc = fmaf(su[s], Kb[(size_t)s * NN + n], acc);
            sv[n] = QF / (acc + EPS_F);
        }
        __syncthreads();
        // u[s] = p / (sum_n v[n] * K[s,n] + eps)   (one warp per s-row, 16 warps)
        for (int s = warp; s < SS; s += 16) {
            float acc = 0.f;
            const float* Kr = Kb + (size_t)s * NN;
            for (int n = lane; n < NN; n += 32)
                acc = fmaf(sv[n], Kr[n], acc);
            #pragma unroll
            for (int o = 16; o; o >>= 1) acc += __shfl_xor_sync(0xffffffffu, acc, o);
            if (lane == 0) su[s] = PF / (acc + EPS_F);
        }
        __syncthreads();
    }

    // final v
    for (int n = tid; n < NN; n += 512) {
        float acc = 0.f;
        #pragma unroll 8
        for (int s = 0; s < SS; s++)
            acc = fmaf(su[s], Kb[(size_t)s * NN + n], acc);
        sv[n] = QF / (acc + EPS_F);
    }
    __syncthreads();

    // Pi[s,n] = u[s] * K[s,n] * v[n]
    float* __restrict__ Pib = Pi + (size_t)b * SS * NN;
    for (int s = 0; s < SS; s++) {
        float us = su[s];
        const float* Kr = Kb + (size_t)s * NN;
        float* Pr = Pib + (size_t)s * NN;
        for (int n = tid; n < NN; n += 512)
            Pr[n] = us * Kr[n] * sv[n];
    }
}

// ---------------- launcher ----------------
extern "C" void kernel_launch(void* const* d_in, const int* in_sizes, int n_in,
                              void* d_out, int out_size) {
    const float* features = (const float*)d_in[0];
    const float* target   = (const float*)d_in[1];
    // defensive: identify by size (features = 51,380,224; target = 65,536)
    if (n_in >= 2 && in_sizes[0] == SS * DD) {
        const float* tmp = features; features = target; target = tmp;
    }
    float* Pi = (float*)d_out;

    norm_target_kernel<<<SS, 128>>>(target);
    feat_norm_kernel<<<(BB * NN) / 8, 256>>>(features);
    gemm_exp_kernel<<<dim3(7, BB), 256>>>(features);
    sinkhorn_kernel<<<BB, 512>>>(Pi);
}

// round 9
// speedup vs baseline: 2.1920x; 2.1920x over previous
#include <cuda_runtime.h>
#include <cuda_bf16.h>
#include <cstdint>

#define BB 128
#define SS 128
#define NN 784
#define DD 512
#define NT 112
#define N_ITERS 10
#define EPS_F 2.2204460492503131e-16f
#define QF (1.0f / 784.0f)
#define PF (1.0f / 128.0f)

// ---------------- device scratch ----------------
__device__ float g_K[(size_t)BB * SS * NN];          // 51.4 MB
__device__ __nv_bfloat16 g_thi[SS * DD];             // normalized target, bf16 hi
__device__ __nv_bfloat16 g_tlo[SS * DD];             // residual lo

// ---------------- helpers ----------------
__device__ __forceinline__ uint32_t smem_u32(const void* p) {
    uint32_t a;
    asm("{ .reg .u64 t; cvta.to.shared.u64 t, %1; cvt.u32.u64 %0, t; }" : "=r"(a) : "l"(p));
    return a;
}
__device__ __forceinline__ unsigned short bf_bits(__nv_bfloat16 h) {
    return *reinterpret_cast<unsigned short*>(&h);
}
__device__ __forceinline__ void ldm_x4(uint32_t* r, uint32_t addr) {
    asm volatile("ldmatrix.sync.aligned.m8n8.x4.shared.b16 {%0,%1,%2,%3}, [%4];"
                 : "=r"(r[0]), "=r"(r[1]), "=r"(r[2]), "=r"(r[3]) : "r"(addr));
}
__device__ __forceinline__ void ldm_x2(uint32_t* r, uint32_t addr) {
    asm volatile("ldmatrix.sync.aligned.m8n8.x2.shared.b16 {%0,%1}, [%2];"
                 : "=r"(r[0]), "=r"(r[1]) : "r"(addr));
}
__device__ __forceinline__ void mma16816(float* c, const uint32_t* a, const uint32_t* b) {
    asm volatile("mma.sync.aligned.m16n8k16.row.col.f32.bf16.bf16.f32 "
                 "{%0,%1,%2,%3}, {%4,%5,%6,%7}, {%8,%9}, {%0,%1,%2,%3};"
                 : "+f"(c[0]), "+f"(c[1]), "+f"(c[2]), "+f"(c[3])
                 : "r"(a[0]), "r"(a[1]), "r"(a[2]), "r"(a[3]), "r"(b[0]), "r"(b[1]));
}
#define CP16(dst, src) \
    asm volatile("cp.async.cg.shared.global [%0], [%1], 16;" :: "r"(dst), "l"(src))
#define CP_COMMIT() asm volatile("cp.async.commit_group;")
#define CP_WAIT0()  asm volatile("cp.async.wait_group 0;")

// ---------------- kernel 1: normalize target + split hi/lo bf16 ----------------
__global__ void norm_target_kernel(const float* __restrict__ t) {
    int s = blockIdx.x;
    int tid = threadIdx.x;  // 128 threads, 4 cols each
    __shared__ float red[4];
    const float4* tr = (const float4*)(t + (size_t)s * DD);
    float4 v = tr[tid];
    float ss = v.x * v.x + v.y * v.y + v.z * v.z + v.w * v.w;
    #pragma unroll
    for (int o = 16; o; o >>= 1) ss += __shfl_xor_sync(0xffffffffu, ss, o);
    if ((tid & 31) == 0) red[tid >> 5] = ss;
    __syncthreads();
    float inv = rsqrtf(red[0] + red[1] + red[2] + red[3]);

    float x[4] = {v.x * inv, v.y * inv, v.z * inv, v.w * inv};
    unsigned short h[4], l[4];
    #pragma unroll
    for (int i = 0; i < 4; i++) {
        __nv_bfloat16 hb = __float2bfloat16(x[i]);
        h[i] = bf_bits(hb);
        l[i] = bf_bits(__float2bfloat16(x[i] - __bfloat162float(hb)));
    }
    *(ushort4*)&g_thi[s * DD + tid * 4] = make_ushort4(h[0], h[1], h[2], h[3]);
    *(ushort4*)&g_tlo[s * DD + tid * 4] = make_ushort4(l[0], l[1], l[2], l[3]);
}

// ---------------- kernel 2: split-bf16 mma.sync GEMM + exp epilogue ----------------
// D[s,n] = sum_k tn[s,k]*fn[n,k] via hh + lh + hl, then K = exp(20*D - 20)
#define KC   64
#define LDA  72            // bf16 elements per smem row (64 + 8 pad)
#define OF_RN 0            // 448 B
#define OF_AH 512
#define OF_AL (OF_AH + 128 * LDA * 2)   // +18432
#define OF_BH (OF_AL + 128 * LDA * 2)
#define OF_BL (OF_BH + NT * LDA * 2)    // +16128
#define GEMM_SMEM (OF_BL + NT * LDA * 2)

__global__ __launch_bounds__(256, 2) void gemm_mma_kernel(const float* __restrict__ f) {
    extern __shared__ unsigned char smem[];
    const int b   = blockIdx.y;
    const int n0  = blockIdx.x * NT;
    const int tid = threadIdx.x;
    const int wid  = tid >> 5;
    const int lane = tid & 31;
    const int sgrp = wid & 3;          // S block of 32
    const int ngrp = wid >> 2;         // N block of 56
    uint32_t sb = smem_u32(smem);
    float* rn_s = (float*)(smem + OF_RN);

    const float* fb = f + (size_t)b * NN * DD;

    // prologue: inverse norms of this CTA's 112 feature rows (one warp per row)
    for (int r = wid; r < NT; r += 8) {
        const float4* fr = (const float4*)(fb + (size_t)(n0 + r) * DD);
        float ssum = 0.f;
        #pragma unroll
        for (int i = lane; i < DD / 4; i += 32) {
            float4 v = fr[i];
            ssum += v.x * v.x + v.y * v.y + v.z * v.z + v.w * v.w;
        }
        #pragma unroll
        for (int o = 16; o; o >>= 1) ssum += __shfl_xor_sync(0xffffffffu, ssum, o);
        if (lane == 0) rn_s[r] = rsqrtf(ssum);
    }
    __syncthreads();

    float acc[2][7][4];
    #pragma unroll
    for (int mt = 0; mt < 2; mt++)
        #pragma unroll
        for (int nt = 0; nt < 7; nt++)
            #pragma unroll
            for (int i = 0; i < 4; i++) acc[mt][nt][i] = 0.f;

    for (int c = 0; c < 8; ++c) {
        if (c) __syncthreads();     // previous chunk fully consumed

        // A tiles: cp.async pre-split bf16 hi/lo (L2-resident, 128 x 64)
        #pragma unroll
        for (int i = tid; i < 1024; i += 256) {
            int s = i >> 3, seg = i & 7;
            int go = s * DD + c * KC + seg * 8;
            uint32_t so = (s * LDA + seg * 8) * 2;
            CP16(sb + OF_AH + so, g_thi + go);
            CP16(sb + OF_AL + so, g_tlo + go);
        }
        CP_COMMIT();

        // B tiles: load f32 features, fold rn, split, STS
        for (int u = tid; u < NT * 8; u += 256) {
            int r = u >> 3, seg = u & 7;
            const float4* src = (const float4*)(fb + (size_t)(n0 + r) * DD + c * KC + seg * 8);
            float4 v0 = src[0], v1 = src[1];
            float rr = rn_s[r];
            float x[8] = {v0.x * rr, v0.y * rr, v0.z * rr, v0.w * rr,
                          v1.x * rr, v1.y * rr, v1.z * rr, v1.w * rr};
            uint32_t H[4], L[4];
            #pragma unroll
            for (int i = 0; i < 4; i++) {
                __nv_bfloat16 h0 = __float2bfloat16(x[2 * i]);
                __nv_bfloat16 h1 = __float2bfloat16(x[2 * i + 1]);
                __nv_bfloat16 l0 = __float2bfloat16(x[2 * i] - __bfloat162float(h0));
                __nv_bfloat16 l1 = __float2bfloat16(x[2 * i + 1] - __bfloat162float(h1));
                H[i] = (uint32_t)bf_bits(h0) | ((uint32_t)bf_bits(h1) << 16);
                L[i] = (uint32_t)bf_bits(l0) | ((uint32_t)bf_bits(l1) << 16);
            }
            uint32_t so = (r * LDA + seg * 8) * 2;
            *(uint4*)(smem + OF_BH + so) = make_uint4(H[0], H[1], H[2], H[3]);
            *(uint4*)(smem + OF_BL + so) = make_uint4(L[0], L[1], L[2], L[3]);
        }
        CP_WAIT0();
        __syncthreads();

        // compute: 4 k-steps of 16
        const int arow = sgrp * 32 + (lane & 15);
        const int acol = (lane >> 4) * 8;
        const int l2 = lane & 15;
        const int bcol = (lane >> 4) * 8;   // threads 16-31 fetch the k+8 half
        #pragma unroll
        for (int ks = 0; ks < 4; ks++) {
            const int kk = ks * 16;
            uint32_t ah[2][4], al[2][4], bf[7][2];
            #pragma unroll
            for (int mt = 0; mt < 2; mt++) {
                uint32_t ao = ((arow + mt * 16) * LDA + kk + acol) * 2;
                ldm_x4(ah[mt], sb + OF_AH + ao);
                ldm_x4(al[mt], sb + OF_AL + ao);
            }
            // B hi fragments: 3 pairs via x4 + 1 via x2
            #pragma unroll
            for (int p = 0; p < 3; p++) {
                uint32_t r4[4];
                ldm_x4(r4, sb + OF_BH + ((ngrp * 56 + p * 16 + l2) * LDA + kk + bcol) * 2);
                bf[2 * p][0] = r4[0]; bf[2 * p][1] = r4[2];
                bf[2 * p + 1][0] = r4[1]; bf[2 * p + 1][1] = r4[3];
            }
            ldm_x2(bf[6], sb + OF_BH + ((ngrp * 56 + 48 + (l2 & 7)) * LDA + kk + (l2 >> 3) * 8) * 2);
            #pragma unroll
            for (int mt = 0; mt < 2; mt++)
                #pragma unroll
                for (int nt = 0; nt < 7; nt++) {
                    mma16816(acc[mt][nt], ah[mt], bf[nt]);   // hi*hi
                    mma16816(acc[mt][nt], al[mt], bf[nt]);   // lo*hi
                }
            // B lo fragments (reuse regs)
            #pragma unroll
            for (int p = 0; p < 3; p++) {
                uint32_t r4[4];
                ldm_x4(r4, sb + OF_BL + ((ngrp * 56 + p * 16 + l2) * LDA + kk + bcol) * 2);
                bf[2 * p][0] = r4[0]; bf[2 * p][1] = r4[2];
                bf[2 * p + 1][0] = r4[1]; bf[2 * p + 1][1] = r4[3];
            }
            ldm_x2(bf[6], sb + OF_BL + ((ngrp * 56 + 48 + (l2 & 7)) * LDA + kk + (l2 >> 3) * 8) * 2);
            #pragma unroll
            for (int mt = 0; mt < 2; mt++)
                #pragma unroll
                for (int nt = 0; nt < 7; nt++)
                    mma16816(acc[mt][nt], ah[mt], bf[nt]);   // hi*lo
        }
    }

    // epilogue: K = exp(20*acc - 20), direct store (rows contiguous in n)
    const int g = lane >> 2;
    const int t2 = (lane & 3) * 2;
    #pragma unroll
    for (int mt = 0; mt < 2; mt++) {
        int srow0 = sgrp * 32 + mt * 16 + g;
        float* kr0 = g_K + ((size_t)b * SS + srow0) * NN + n0 + ngrp * 56;
        float* kr1 = kr0 + 8 * NN;
        #pragma unroll
        for (int nt = 0; nt < 7; nt++) {
            int cc = nt * 8 + t2;
            kr0[cc]     = __expf(fmaf(acc[mt][nt][0], 20.f, -20.f));
            kr0[cc + 1] = __expf(fmaf(acc[mt][nt][1], 20.f, -20.f));
            kr1[cc]     = __expf(fmaf(acc[mt][nt][2], 20.f, -20.f));
            kr1[cc + 1] = __expf(fmaf(acc[mt][nt][3], 20.f, -20.f));
        }
    }
}

// ---------------- kernel 3: Sinkhorn + Pi, one CTA per batch ----------------
__global__ __launch_bounds__(1024, 1) void sinkhorn_kernel(float* __restrict__ Pi) {
    const int b = blockIdx.x;
    const int tid = threadIdx.x;
    const int warp = tid >> 5;
    const int lane = tid & 31;
    const float* __restrict__ Kb = g_K + (size_t)b * SS * NN;

    __shared__ float su[SS];
    __shared__ float sv[NN];
    if (tid < SS) su[tid] = 1.0f;
    __syncthreads();

    for (int it = 0; it < N_ITERS; it++) {
        if (tid < NN) {
            const float* Kc = Kb + tid;
            float a0 = 0.f, a1 = 0.f, a2 = 0.f, a3 = 0.f;
            #pragma unroll 8
            for (int s = 0; s < SS; s += 4) {
                a0 = fmaf(su[s + 0], Kc[(size_t)(s + 0) * NN], a0);
                a1 = fmaf(su[s + 1], Kc[(size_t)(s + 1) * NN], a1);
                a2 = fmaf(su[s + 2], Kc[(size_t)(s + 2) * NN], a2);
                a3 = fmaf(su[s + 3], Kc[(size_t)(s + 3) * NN], a3);
            }
            sv[tid] = QF / (((a0 + a1) + (a2 + a3)) + EPS_F);
        }
        __syncthreads();
        for (int s = warp; s < SS; s += 32) {
            const float* Kr = Kb + (size_t)s * NN;
            float a0 = 0.f, a1 = 0.f;
            for (int n = lane; n < NN; n += 64) {
                a0 = fmaf(sv[n], Kr[n], a0);
                int n2 = n + 32;
                if (n2 < NN) a1 = fmaf(sv[n2], Kr[n2], a1);
            }
            float a = a0 + a1;
            #pragma unroll
            for (int o = 16; o; o >>= 1) a += __shfl_xor_sync(0xffffffffu, a, o);
            if (lane == 0) su[s] = PF / (a + EPS_F);
        }
        __syncthreads();
    }

    if (tid < NN) {
        const float* Kc = Kb + tid;
        float a0 = 0.f, a1 = 0.f, a2 = 0.f, a3 = 0.f;
        #pragma unroll 8
        for (int s = 0; s < SS; s += 4) {
            a0 = fmaf(su[s + 0], Kc[(size_t)(s + 0) * NN], a0);
            a1 = fmaf(su[s + 1], Kc[(size_t)(s + 1) * NN], a1);
            a2 = fmaf(su[s + 2], Kc[(size_t)(s + 2) * NN], a2);
            a3 = fmaf(su[s + 3], Kc[(size_t)(s + 3) * NN], a3);
        }
        sv[tid] = QF / (((a0 + a1) + (a2 + a3)) + EPS_F);
    }
    __syncthreads();

    if (tid < NN) {
        float vv = sv[tid];
        const float* Kc = Kb + tid;
        float* Pc = Pi + (size_t)b * SS * NN + tid;
        #pragma unroll 4
        for (int s = 0; s < SS; s++)
            Pc[(size_t)s * NN] = su[s] * Kc[(size_t)s * NN] * vv;
    }
}

// ---------------- launcher ----------------
extern "C" void kernel_launch(void* const* d_in, const int* in_sizes, int n_in,
                              void* d_out, int out_size) {
    const float* features = (const float*)d_in[0];
    const float* target   = (const float*)d_in[1];
    if (n_in >= 2 && in_sizes[0] == SS * DD) {
        const float* tmp = features; features = target; target = tmp;
    }
    float* Pi = (float*)d_out;

    cudaFuncSetAttribute(gemm_mma_kernel,
                         cudaFuncAttributeMaxDynamicSharedMemorySize, GEMM_SMEM);

    norm_target_kernel<<<SS, 128>>>(target);
    gemm_mma_kernel<<<dim3(7, BB), 256, GEMM_SMEM>>>(features);
    sinkhorn_kernel<<<BB, 1024>>>(Pi);
}